// round 8
// baseline (speedup 1.0000x reference)
#include <cuda_runtime.h>
#include <cstdint>
#include <cstddef>

#define NTOK   49
#define CDIM   128
#define HEADS  4
#define HD     32
#define MAXTOK (8192 * 49)

// scratch (device globals: allocation-free rule)
__device__ float g_qkv[(size_t)MAXTOK * 384];   // [token][384]
__device__ float g_o  [(size_t)MAXTOK * 128];   // [token][128]

// ---------------------------------------------------------------- helpers
__device__ __forceinline__ float tf32r(float x) {
    uint32_t u;
    asm("cvt.rna.tf32.f32 %0, %1;" : "=r"(u) : "f"(x));
    return __uint_as_float(u);
}
// logical col -> physical col within its 8-group: [0,4,1,5,2,6,3,7]
__device__ __forceinline__ int permc(int c) {
    return (c & ~7) | (((c & 3) << 1) | ((c >> 2) & 1));
}
__device__ __forceinline__ void mma8(float* d, const uint32_t* a, const uint32_t* b) {
    asm volatile(
        "mma.sync.aligned.m16n8k8.row.col.f32.tf32.tf32.f32 "
        "{%0,%1,%2,%3}, {%4,%5,%6,%7}, {%8,%9}, {%0,%1,%2,%3};\n"
        : "+f"(d[0]), "+f"(d[1]), "+f"(d[2]), "+f"(d[3])
        : "r"(a[0]), "r"(a[1]), "r"(a[2]), "r"(a[3]), "r"(b[0]), "r"(b[1]));
}
__device__ __forceinline__ void ldA(uint32_t* af, const float* base, int row, int stride, int kk2t) {
    float2 p0 = *(const float2*)(base + row * stride + kk2t);
    float2 p1 = *(const float2*)(base + (row + 8) * stride + kk2t);
    af[0] = __float_as_uint(p0.x);
    af[1] = __float_as_uint(p1.x);
    af[2] = __float_as_uint(p0.y);
    af[3] = __float_as_uint(p1.y);
}
__device__ __forceinline__ void ldB(uint32_t* bf, const float* base, int row, int stride, int kk2t) {
    float2 q = *(const float2*)(base + row * stride + kk2t);
    bf[0] = __float_as_uint(q.x);
    bf[1] = __float_as_uint(q.y);
}
__device__ __forceinline__ void st_ipair8(float* dst, float4 lo, float4 hi) {
    float4 o0, o1;
    o0.x = tf32r(lo.x); o0.y = tf32r(hi.x); o0.z = tf32r(lo.y); o0.w = tf32r(hi.y);
    o1.x = tf32r(lo.z); o1.y = tf32r(hi.z); o1.z = tf32r(lo.w); o1.w = tf32r(hi.w);
    *(float4*)(dst)     = o0;
    *(float4*)(dst + 4) = o1;
}

// ================================================================ K1 / K3 GEMM
// C[64 x 128] = A[64 x 128] * W[128 x 128]^T   (tf32 mma, ipair smem layout)
#define GROW   136                  // ipair smem stride (mod 32 == 8)
#define G_XS   0                    // 64 * 136 = 8704 floats (aliased by Cs stride 132)
#define G_WS   (64 * GROW)
#define G_SMEM ((G_WS + 128 * GROW) * 4)   // 104448 bytes

template <bool PROJ>
__global__ __launch_bounds__(256, 2)
void gemm_kernel(const float* __restrict__ a_glob,   // used when PROJ (g_o is device sym)
                 const float* __restrict__ w,
                 const float* __restrict__ pb,
                 float* __restrict__ outp,
                 int Mtot)
{
    extern __shared__ float sm[];
    float* Xs = sm + G_XS;
    float* Ws = sm + G_WS;
    const int tid  = threadIdx.x;
    const int wid  = tid >> 5;
    const int lane = tid & 31;
    const int g    = lane >> 2;
    const int t    = lane & 3;
    const int t2   = t << 1;
    const int mblk = blockIdx.x;
    const int nblk = blockIdx.y;
    const int rowbase = mblk * 64;
    const int astride = PROJ ? 128 : CDIM;
    const float* A = PROJ ? g_o : a_glob;

    // stage A tile (64 x 128) into ipair layout
    for (int i = tid; i < 64 * 16; i += 256) {
        int r = i >> 4, c8 = (i & 15) << 3;
        int grow = rowbase + r; if (grow >= Mtot) grow = Mtot - 1;
        const float* src = A + (size_t)grow * astride + c8;
        st_ipair8(Xs + r * GROW + c8, *(const float4*)src, *(const float4*)(src + 4));
    }
    // stage W tile (128 x 128) into ipair layout
    for (int i = tid; i < 128 * 16; i += 256) {
        int n = i >> 4, c8 = (i & 15) << 3;
        const float* src = w + (size_t)(nblk * 128 + n) * CDIM + c8;
        st_ipair8(Ws + n * GROW + c8, *(const float4*)src, *(const float4*)(src + 4));
    }
    __syncthreads();

    const int mh = wid >> 2;        // 0..1 : 32-row half
    const int nq = wid & 3;         // 0..3 : 32-col quarter
    float acc[2][4][4];
    #pragma unroll
    for (int mi = 0; mi < 2; ++mi)
        #pragma unroll
        for (int nt = 0; nt < 4; ++nt)
            #pragma unroll
            for (int e = 0; e < 4; ++e) acc[mi][nt][e] = 0.f;

    #pragma unroll
    for (int k8 = 0; k8 < 16; ++k8) {       // k ascending 0..127 (order matches fused)
        const int kp = k8 * 8 + t2;
        uint32_t af0[4], af1[4];
        ldA(af0, Xs, mh * 32 + g,      GROW, kp);
        ldA(af1, Xs, mh * 32 + 16 + g, GROW, kp);
        #pragma unroll
        for (int nt = 0; nt < 4; ++nt) {
            uint32_t bf[2];
            ldB(bf, Ws, nq * 32 + nt * 8 + g, GROW, kp);
            mma8(acc[0][nt], af0, bf);
            mma8(acc[1][nt], af1, bf);
        }
    }
    __syncthreads();

    // stash C into smem (stride 132, aliases Xs region), then coalesced store
    float* Cs = sm;
    #pragma unroll
    for (int mi = 0; mi < 2; ++mi)
        #pragma unroll
        for (int nt = 0; nt < 4; ++nt)
            #pragma unroll
            for (int e = 0; e < 4; ++e) {
                int row = mh * 32 + mi * 16 + g + (e >> 1) * 8;
                int col = nq * 32 + nt * 8 + 2 * t + (e & 1);
                Cs[row * 132 + col] = acc[mi][nt][e];
            }
    __syncthreads();
    for (int i = tid; i < 64 * 32; i += 256) {
        int r = i >> 5, c4 = (i & 31) << 2;
        int grow = rowbase + r;
        if (grow < Mtot) {
            float4 v = *(const float4*)(Cs + r * 132 + c4);
            if (PROJ) {
                float4 bb = *(const float4*)(pb + c4);
                v.x += bb.x; v.y += bb.y; v.z += bb.z; v.w += bb.w;
                *(float4*)(outp + (size_t)grow * 128 + c4) = v;
            } else {
                *(float4*)(g_qkv + (size_t)grow * 384 + nblk * 128 + c4) = v;
            }
        }
    }
}

// ================================================================ K2: attention
// one CTA per (window, head); 256 threads (8 warps)
#define QROW2  40
#define VROW2  56
#define PROW2  56
#define OROW2  36
#define OFF2_Q 0                       // 64*40 = 2560 (later aliased by O, stride 36)
#define OFF2_K (OFF2_Q + 64 * QROW2)   // 56*40 = 2240
#define OFF2_V (OFF2_K + 56 * QROW2)   // 32*56 = 1792
#define OFF2_P (OFF2_V + HD * VROW2)   // 64*56 = 3584
#define OFF2_M (OFF2_P + 64 * PROW2)   // 2404
#define OFF2_B (OFF2_M + 2404)         // 676
#define OFF2_R (OFF2_B + 676)          // 2404
#define SMEM2  ((OFF2_R + 2404) * 4)   // 62640 bytes

__global__ __launch_bounds__(256)
void attn_kernel(const float* __restrict__ mask,
                 const float* __restrict__ bias_table,
                 const float* __restrict__ alpha,
                 const int*   __restrict__ rel_idx,
                 int nwin)
{
    extern __shared__ float sm[];
    const int b    = blockIdx.x;
    const int h    = blockIdx.y;
    const int tid  = threadIdx.x;
    const int wid  = tid >> 5;
    const int lane = tid & 31;
    const int g    = lane >> 2;
    const int t    = lane & 3;
    const int t2   = t << 1;

    float* Qs = sm + OFF2_Q;
    float* Ks = sm + OFF2_K;
    float* Vs = sm + OFF2_V;
    float* Ps = sm + OFF2_P;
    float* Ms = sm + OFF2_M;
    float* Bt = sm + OFF2_B;
    int*   Ri = (int*)(sm + OFF2_R);
    float* Os = sm + OFF2_Q;      // O aliases Q (Q dead after S-mma)

    // zero V (incl. token-pad cols) before scattered fills
    for (int i = tid; i < HD * VROW2; i += 256) Vs[i] = 0.f;
    __syncthreads();

    // stage q, k (head-dim ipair-permuted), v (transposed, token ipair-permuted, tf32)
    const float* qb = g_qkv + (size_t)(b * NTOK) * 384 + h * HD;
    for (int i = tid; i < NTOK * HD; i += 256) {
        int r = i >> 5, d = i & 31;
        int col = permc(d);
        Qs[r * QROW2 + col] = qb[(size_t)r * 384 + d];
        Ks[r * QROW2 + col] = qb[(size_t)r * 384 + 128 + d];
        Vs[d * VROW2 + permc(r)] = tf32r(qb[(size_t)r * 384 + 256 + d]);
    }
    {
        const float* mb = mask + (size_t)(b % nwin) * (NTOK * NTOK);
        for (int i = tid; i < NTOK * NTOK; i += 256) Ms[i] = mb[i];   // odd base: scalar
        for (int i = tid; i < 600; i += 256) *(int4*)(Ri + i * 4) = *(const int4*)(rel_idx + i * 4);
        if (tid == 0) Ri[2400] = rel_idx[2400];
        for (int i = tid; i < 169; i += 256) *(float4*)(Bt + i * 4) = *(const float4*)(bias_table + i * 4);
    }
    __syncthreads();

    // L2 normalize q (alpha folded) / k; 4-row ILP
    {
        const bool isQ = (wid < 4);
        const int  part = wid & 3;
        const float sc = isQ ? alpha[h] : 1.f;
        float* T = isQ ? Qs : Ks;
        const int rs = part * 13;
        const int re = min(rs + 13, NTOK);
        for (int r = rs; r < re; r += 4) {
            float v[4], ss[4]; int rr[4];
            #pragma unroll
            for (int j = 0; j < 4; ++j) {
                rr[j] = min(r + j, re - 1);
                v[j]  = T[rr[j] * QROW2 + lane];
                ss[j] = v[j] * v[j];
            }
            #pragma unroll
            for (int o = 16; o > 0; o >>= 1) {
                #pragma unroll
                for (int j = 0; j < 4; ++j) ss[j] += __shfl_xor_sync(0xffffffffu, ss[j], o);
            }
            #pragma unroll
            for (int j = 0; j < 4; ++j) {
                if (r + j < re) {
                    float inv = sc / (sqrtf(ss[j]) + 1e-6f);
                    T[rr[j] * QROW2 + lane] = tf32r(v[j] * inv);
                }
            }
        }
    }
    __syncthreads();

    // S = q_hat k_hat^T + rpb + mask; pad cols j>=NTOK get -1e30
    if (wid < 7) {
        const int nt = wid;
        uint32_t bfv[4][2];
        #pragma unroll
        for (int k8 = 0; k8 < 4; ++k8)
            ldB(bfv[k8], Ks, nt * 8 + g, QROW2, k8 * 8 + t2);
        #pragma unroll
        for (int mt = 0; mt < 4; ++mt) {
            float c[4] = {0.f, 0.f, 0.f, 0.f};
            #pragma unroll
            for (int k8 = 0; k8 < 4; ++k8) {
                uint32_t af[4];
                ldA(af, Qs, mt * 16 + g, QROW2, k8 * 8 + t2);
                mma8(c, af, bfv[k8]);
            }
            #pragma unroll
            for (int e = 0; e < 4; ++e) {
                int i = mt * 16 + g + (e >> 1) * 8;
                int j = nt * 8 + 2 * t + (e & 1);
                float v;
                if (j >= NTOK)       v = -1e30f;
                else if (i < NTOK)   v = c[e] + Bt[Ri[i * NTOK + j] * HEADS + h] + Ms[i * NTOK + j];
                else                 v = c[e];
                Ps[i * PROW2 + permc(j)] = v;
            }
        }
    }
    __syncthreads();

    // row softmax (no max-subtract; logits bounded); pads -1e30 -> exp 0
    {
        for (int i0 = wid; i0 < NTOK; i0 += 16) {
            const int ia = i0;
            const int ib = i0 + 8;
            const bool hasb = (ib < NTOK);
            const int ibc = hasb ? ib : ia;
            float e1a = __expf(Ps[ia * PROW2 + lane]);
            float e2a = (lane < 24) ? __expf(Ps[ia * PROW2 + 32 + lane]) : 0.f;
            float e1b = __expf(Ps[ibc * PROW2 + lane]);
            float e2b = (lane < 24) ? __expf(Ps[ibc * PROW2 + 32 + lane]) : 0.f;
            float sa = e1a + e2a;
            float sb = e1b + e2b;
            #pragma unroll
            for (int o = 16; o > 0; o >>= 1) {
                sa += __shfl_xor_sync(0xffffffffu, sa, o);
                sb += __shfl_xor_sync(0xffffffffu, sb, o);
            }
            float inva = 1.f / sa;
            Ps[ia * PROW2 + lane] = tf32r(e1a * inva);
            if (lane < 24) Ps[ia * PROW2 + 32 + lane] = tf32r(e2a * inva);
            if (hasb) {
                float invb = 1.f / sb;
                Ps[ib * PROW2 + lane] = tf32r(e1b * invb);
                if (lane < 24) Ps[ib * PROW2 + 32 + lane] = tf32r(e2b * invb);
            }
        }
    }
    __syncthreads();

    // O = P V  (V^T layout): 4 nt x 4 mt over 8 warps; O -> Os (stride 36, logical cols)
    {
        const int nt  = wid >> 1;
        const int mt0 = (wid & 1) * 2;
        uint32_t bfv[7][2];
        #pragma unroll
        for (int k8 = 0; k8 < 7; ++k8)
            ldB(bfv[k8], Vs, nt * 8 + g, VROW2, k8 * 8 + t2);
        #pragma unroll
        for (int mi = 0; mi < 2; ++mi) {
            const int mt = mt0 + mi;
            float c[4] = {0.f, 0.f, 0.f, 0.f};
            #pragma unroll
            for (int k8 = 0; k8 < 7; ++k8) {
                uint32_t af[4];
                ldA(af, Ps, mt * 16 + g, PROW2, k8 * 8 + t2);
                mma8(c, af, bfv[k8]);
            }
            #pragma unroll
            for (int e = 0; e < 4; ++e) {
                int i = mt * 16 + g + (e >> 1) * 8;
                if (i >= NTOK) continue;
                int d = nt * 8 + 2 * t + (e & 1);
                Os[i * OROW2 + d] = tf32r(c[e]);
            }
        }
    }
    __syncthreads();

    // coalesced O write to global
    for (int i = tid; i < NTOK * 8; i += 256) {
        int r = i >> 3, c4 = (i & 7) << 2;
        *(float4*)(g_o + (size_t)(b * NTOK + r) * 128 + h * HD + c4) =
            *(const float4*)(Os + r * OROW2 + c4);
    }
}

// ================================================================ launch
extern "C" void kernel_launch(void* const* d_in, const int* in_sizes, int n_in,
                              void* d_out, int out_size) {
    const float* x    = (const float*)d_in[0];
    const float* mask = (const float*)d_in[1];
    const float* qkvw = (const float*)d_in[2];
    const float* pw   = (const float*)d_in[3];
    const float* pb   = (const float*)d_in[4];
    const float* bt   = (const float*)d_in[5];
    const float* al   = (const float*)d_in[6];
    const int*   ri   = (const int*)d_in[7];
    float* out = (float*)d_out;

    int B    = in_sizes[0] / (NTOK * CDIM);
    int NW   = in_sizes[1] / (NTOK * NTOK);
    int Mtot = B * NTOK;
    int mblks = (Mtot + 63) / 64;

    cudaFuncSetAttribute(gemm_kernel<false>, cudaFuncAttributeMaxDynamicSharedMemorySize, G_SMEM);
    cudaFuncSetAttribute(gemm_kernel<true>,  cudaFuncAttributeMaxDynamicSharedMemorySize, G_SMEM);
    cudaFuncSetAttribute(attn_kernel,        cudaFuncAttributeMaxDynamicSharedMemorySize, SMEM2);

    gemm_kernel<false><<<dim3(mblks, 3), 256, G_SMEM>>>(x, qkvw, nullptr, nullptr, Mtot);
    attn_kernel<<<dim3(B, HEADS), 256, SMEM2>>>(mask, bt, al, ri, NW);
    gemm_kernel<true><<<dim3(mblks, 1), 256, G_SMEM>>>(nullptr, pw, pb, out, Mtot);
}

// round 10
// speedup vs baseline: 1.3884x; 1.3884x over previous
#include <cuda_runtime.h>
#include <cstdint>
#include <cstddef>

#define NTOK   49
#define CDIM   128
#define HEADS  4
#define HD     32
#define MAXTOK (8192 * 49)

// scratch (device globals: allocation-free rule)
__device__ float g_qkv[(size_t)MAXTOK * 384];   // [token][384]
__device__ float g_o  [(size_t)MAXTOK * 128];   // [token][128]
__device__ float g_rpb[HEADS * NTOK * NTOK];    // [h][i][j] precomputed bias gather

// ---------------------------------------------------------------- helpers
__device__ __forceinline__ float tf32r(float x) {
    uint32_t u;
    asm("cvt.rna.tf32.f32 %0, %1;" : "=r"(u) : "f"(x));
    return __uint_as_float(u);
}
// logical col -> physical col within its 8-group: [0,4,1,5,2,6,3,7]
__device__ __forceinline__ int permc(int c) {
    return (c & ~7) | (((c & 3) << 1) | ((c >> 2) & 1));
}
__device__ __forceinline__ void mma8(float* d, const uint32_t* a, const uint32_t* b) {
    asm volatile(
        "mma.sync.aligned.m16n8k8.row.col.f32.tf32.tf32.f32 "
        "{%0,%1,%2,%3}, {%4,%5,%6,%7}, {%8,%9}, {%0,%1,%2,%3};\n"
        : "+f"(d[0]), "+f"(d[1]), "+f"(d[2]), "+f"(d[3])
        : "r"(a[0]), "r"(a[1]), "r"(a[2]), "r"(a[3]), "r"(b[0]), "r"(b[1]));
}
__device__ __forceinline__ void ldA(uint32_t* af, const float* base, int row, int stride, int kk2t) {
    float2 p0 = *(const float2*)(base + row * stride + kk2t);
    float2 p1 = *(const float2*)(base + (row + 8) * stride + kk2t);
    af[0] = __float_as_uint(p0.x);
    af[1] = __float_as_uint(p1.x);
    af[2] = __float_as_uint(p0.y);
    af[3] = __float_as_uint(p1.y);
}
__device__ __forceinline__ void ldB(uint32_t* bf, const float* base, int row, int stride, int kk2t) {
    float2 q = *(const float2*)(base + row * stride + kk2t);
    bf[0] = __float_as_uint(q.x);
    bf[1] = __float_as_uint(q.y);
}
__device__ __forceinline__ void st_ipair8(float* dst, float4 lo, float4 hi) {
    float4 o0, o1;
    o0.x = tf32r(lo.x); o0.y = tf32r(hi.x); o0.z = tf32r(lo.y); o0.w = tf32r(hi.y);
    o1.x = tf32r(lo.z); o1.y = tf32r(hi.z); o1.z = tf32r(lo.w); o1.w = tf32r(hi.w);
    *(float4*)(dst)     = o0;
    *(float4*)(dst + 4) = o1;
}

// ================================================================ K0: rpb precompute
__global__ void rpb_kernel(const float* __restrict__ bias_table,
                           const int*   __restrict__ rel_idx) {
    int idx = blockIdx.x * 256 + threadIdx.x;
    if (idx < NTOK * NTOK) {
        int r = rel_idx[idx];
        #pragma unroll
        for (int h = 0; h < HEADS; ++h)
            g_rpb[h * (NTOK * NTOK) + idx] = bias_table[r * HEADS + h];
    }
}

// ================================================================ K1 / K3 GEMM
// C[64 x 128] = A[64 x 128] * W[128 x 128]^T  (tf32 mma, ipair smem, W k-chunked)
#define AROW   136                  // A stride (mod 32 == 8)
#define WKR    40                   // W chunk stride (mod 32 == 8)
#define K1_A   0                    // 64*136  = 8704 floats
#define K1_W   (64 * AROW)          // 128*40  = 5120 floats
#define K1_SMEM ((K1_W + 128 * WKR) * 4)   // 55296 bytes -> 4 CTAs/SM

template <bool PROJ>
__global__ __launch_bounds__(256, 4)
void gemm_kernel(const float* __restrict__ a_glob,
                 const float* __restrict__ w,
                 const float* __restrict__ pb,
                 float* __restrict__ outp,
                 int Mtot)
{
    extern __shared__ float sm[];
    float* Xs = sm + K1_A;
    float* Ws = sm + K1_W;
    const int tid  = threadIdx.x;
    const int wid  = tid >> 5;
    const int lane = tid & 31;
    const int g    = lane >> 2;
    const int t    = lane & 3;
    const int t2   = t << 1;
    const int mblk = blockIdx.x;
    const int nblk = blockIdx.y;
    const int rowbase = mblk * 64;
    const float* A = PROJ ? g_o : a_glob;

    // stage A tile (64 x 128, full k) into ipair layout
    for (int i = tid; i < 64 * 16; i += 256) {
        int r = i >> 4, c8 = (i & 15) << 3;
        int grow = rowbase + r; if (grow >= Mtot) grow = Mtot - 1;
        const float* src = A + (size_t)grow * CDIM + c8;
        st_ipair8(Xs + r * AROW + c8, *(const float4*)src, *(const float4*)(src + 4));
    }

    const int mh = wid >> 2;        // 0..1 : 32-row half
    const int nq = wid & 3;         // 0..3 : 32-col quarter
    float acc[2][4][4];
    #pragma unroll
    for (int mi = 0; mi < 2; ++mi)
        #pragma unroll
        for (int nt = 0; nt < 4; ++nt)
            #pragma unroll
            for (int e = 0; e < 4; ++e) acc[mi][nt][e] = 0.f;

    for (int kc = 0; kc < 4; ++kc) {          // stream W in k-chunks of 32
        __syncthreads();
        for (int i = tid; i < 128 * 4; i += 256) {
            int n = i >> 2, c8 = (i & 3) << 3;
            const float* src = w + (size_t)(nblk * 128 + n) * CDIM + kc * 32 + c8;
            st_ipair8(Ws + n * WKR + c8, *(const float4*)src, *(const float4*)(src + 4));
        }
        __syncthreads();
        #pragma unroll
        for (int k8 = 0; k8 < 4; ++k8) {
            const int kp = k8 * 8 + t2;
            uint32_t af0[4], af1[4];
            ldA(af0, Xs, mh * 32 + g,      AROW, kc * 32 + kp);
            ldA(af1, Xs, mh * 32 + 16 + g, AROW, kc * 32 + kp);
            #pragma unroll
            for (int nt = 0; nt < 4; ++nt) {
                uint32_t bf[2];
                ldB(bf, Ws, nq * 32 + nt * 8 + g, WKR, kp);
                mma8(acc[0][nt], af0, bf);
                mma8(acc[1][nt], af1, bf);
            }
        }
    }
    __syncthreads();

    // stash C into smem (stride 132, aliases Xs region), then coalesced store
    float* Cs = sm;
    #pragma unroll
    for (int mi = 0; mi < 2; ++mi)
        #pragma unroll
        for (int nt = 0; nt < 4; ++nt)
            #pragma unroll
            for (int e = 0; e < 4; ++e) {
                int row = mh * 32 + mi * 16 + g + (e >> 1) * 8;
                int col = nq * 32 + nt * 8 + 2 * t + (e & 1);
                Cs[row * 132 + col] = acc[mi][nt][e];
            }
    __syncthreads();
    for (int i = tid; i < 64 * 32; i += 256) {
        int r = i >> 5, c4 = (i & 31) << 2;
        int grow = rowbase + r;
        if (grow < Mtot) {
            float4 v = *(const float4*)(Cs + r * 132 + c4);
            if (PROJ) {
                float4 bb = *(const float4*)(pb + c4);
                v.x += bb.x; v.y += bb.y; v.z += bb.z; v.w += bb.w;
                *(float4*)(outp + (size_t)grow * 128 + c4) = v;
            } else {
                *(float4*)(g_qkv + (size_t)grow * 384 + nblk * 128 + c4) = v;
            }
        }
    }
}

// ================================================================ K2: attention
// one CTA per (window, head); 256 threads; rpb/mask read directly from global
#define QROW2  40
#define VROW2  56
#define PROW2  56
#define OROW2  36
#define OFF2_Q 0                       // 64*40 = 2560 (later aliased by O, stride 36)
#define OFF2_K (OFF2_Q + 64 * QROW2)   // 56*40 = 2240
#define OFF2_V (OFF2_K + 56 * QROW2)   // 32*56 = 1792
#define OFF2_P (OFF2_V + HD * VROW2)   // 64*56 = 3584
#define SMEM2  ((OFF2_P + 64 * PROW2) * 4)   // 40704 bytes -> 5 CTAs/SM

__global__ __launch_bounds__(256)
void attn_kernel(const float* __restrict__ mask,
                 const float* __restrict__ alpha,
                 int nwin)
{
    extern __shared__ float sm[];
    const int b    = blockIdx.x;
    const int h    = blockIdx.y;
    const int tid  = threadIdx.x;
    const int wid  = tid >> 5;
    const int lane = tid & 31;
    const int g    = lane >> 2;
    const int t    = lane & 3;
    const int t2   = t << 1;

    float* Qs = sm + OFF2_Q;
    float* Ks = sm + OFF2_K;
    float* Vs = sm + OFF2_V;
    float* Ps = sm + OFF2_P;
    float* Os = sm + OFF2_Q;      // O aliases Q (Q dead after S-mma)

    const float* mb  = mask + (size_t)(b % nwin) * (NTOK * NTOK);
    const float* rpb = g_rpb + h * (NTOK * NTOK);

    // zero V (incl. token-pad cols) before scattered fills
    for (int i = tid; i < HD * VROW2; i += 256) Vs[i] = 0.f;
    __syncthreads();

    // stage q, k (head-dim ipair-permuted), v (transposed, token ipair-permuted, tf32)
    const float* qb = g_qkv + (size_t)(b * NTOK) * 384 + h * HD;
    for (int i = tid; i < NTOK * HD; i += 256) {
        int r = i >> 5, d = i & 31;
        int col = permc(d);
        Qs[r * QROW2 + col] = qb[(size_t)r * 384 + d];
        Ks[r * QROW2 + col] = qb[(size_t)r * 384 + 128 + d];
        Vs[d * VROW2 + permc(r)] = tf32r(qb[(size_t)r * 384 + 256 + d]);
    }
    __syncthreads();

    // L2 normalize q (alpha folded) / k; 4-row ILP
    {
        const bool isQ = (wid < 4);
        const int  part = wid & 3;
        const float sc = isQ ? alpha[h] : 1.f;
        float* T = isQ ? Qs : Ks;
        const int rs = part * 13;
        const int re = min(rs + 13, NTOK);
        for (int r = rs; r < re; r += 4) {
            float v[4], ss[4]; int rr[4];
            #pragma unroll
            for (int j = 0; j < 4; ++j) {
                rr[j] = min(r + j, re - 1);
                v[j]  = T[rr[j] * QROW2 + lane];
                ss[j] = v[j] * v[j];
            }
            #pragma unroll
            for (int o = 16; o > 0; o >>= 1) {
                #pragma unroll
                for (int j = 0; j < 4; ++j) ss[j] += __shfl_xor_sync(0xffffffffu, ss[j], o);
            }
            #pragma unroll
            for (int j = 0; j < 4; ++j) {
                if (r + j < re) {
                    float inv = sc / (sqrtf(ss[j]) + 1e-6f);
                    T[rr[j] * QROW2 + lane] = tf32r(v[j] * inv);
                }
            }
        }
    }
    __syncthreads();

    // S = q_hat k_hat^T + rpb + mask (both straight from global); pad cols -> -1e30
    if (wid < 7) {
        const int nt = wid;
        uint32_t bfv[4][2];
        #pragma unroll
        for (int k8 = 0; k8 < 4; ++k8)
            ldB(bfv[k8], Ks, nt * 8 + g, QROW2, k8 * 8 + t2);
        #pragma unroll
        for (int mt = 0; mt < 4; ++mt) {
            float c[4] = {0.f, 0.f, 0.f, 0.f};
            #pragma unroll
            for (int k8 = 0; k8 < 4; ++k8) {
                uint32_t af[4];
                ldA(af, Qs, mt * 16 + g, QROW2, k8 * 8 + t2);
                mma8(c, af, bfv[k8]);
            }
            #pragma unroll
            for (int e = 0; e < 4; ++e) {
                int i = mt * 16 + g + (e >> 1) * 8;
                int j = nt * 8 + 2 * t + (e & 1);
                float v;
                if (j >= NTOK)       v = -1e30f;
                else if (i < NTOK)   v = c[e] + rpb[i * NTOK + j] + mb[i * NTOK + j];
                else                 v = c[e];
                Ps[i * PROW2 + permc(j)] = v;
            }
        }
    }
    __syncthreads();

    // row softmax (no max-subtract; logits bounded); pads -1e30 -> exp 0
    {
        for (int i0 = wid; i0 < NTOK; i0 += 16) {
            const int ia = i0;
            const int ib = i0 + 8;
            const bool hasb = (ib < NTOK);
            const int ibc = hasb ? ib : ia;
            float e1a = __expf(Ps[ia * PROW2 + lane]);
            float e2a = (lane < 24) ? __expf(Ps[ia * PROW2 + 32 + lane]) : 0.f;
            float e1b = __expf(Ps[ibc * PROW2 + lane]);
            float e2b = (lane < 24) ? __expf(Ps[ibc * PROW2 + 32 + lane]) : 0.f;
            float sa = e1a + e2a;
            float sb = e1b + e2b;
            #pragma unroll
            for (int o = 16; o > 0; o >>= 1) {
                sa += __shfl_xor_sync(0xffffffffu, sa, o);
                sb += __shfl_xor_sync(0xffffffffu, sb, o);
            }
            float inva = 1.f / sa;
            Ps[ia * PROW2 + lane] = tf32r(e1a * inva);
            if (lane < 24) Ps[ia * PROW2 + 32 + lane] = tf32r(e2a * inva);
            if (hasb) {
                float invb = 1.f / sb;
                Ps[ib * PROW2 + lane] = tf32r(e1b * invb);
                if (lane < 24) Ps[ib * PROW2 + 32 + lane] = tf32r(e2b * invb);
            }
        }
    }
    __syncthreads();

    // O = P V  (V^T layout): 4 nt x 4 mt over 8 warps; O -> Os (stride 36, logical cols)
    {
        const int nt  = wid >> 1;
        const int mt0 = (wid & 1) * 2;
        uint32_t bfv[7][2];
        #pragma unroll
        for (int k8 = 0; k8 < 7; ++k8)
            ldB(bfv[k8], Vs, nt * 8 + g, VROW2, k8 * 8 + t2);
        #pragma unroll
        for (int mi = 0; mi < 2; ++mi) {
            const int mt = mt0 + mi;
            float c[4] = {0.f, 0.f, 0.f, 0.f};
            #pragma unroll
            for (int k8 = 0; k8 < 7; ++k8) {
                uint32_t af[4];
                ldA(af, Ps, mt * 16 + g, PROW2, k8 * 8 + t2);
                mma8(c, af, bfv[k8]);
            }
            #pragma unroll
            for (int e = 0; e < 4; ++e) {
                int i = mt * 16 + g + (e >> 1) * 8;
                if (i >= NTOK) continue;
                int d = nt * 8 + 2 * t + (e & 1);
                Os[i * OROW2 + d] = tf32r(c[e]);
            }
        }
    }
    __syncthreads();

    // coalesced O write to global
    for (int i = tid; i < NTOK * 8; i += 256) {
        int r = i >> 3, c4 = (i & 7) << 2;
        *(float4*)(g_o + (size_t)(b * NTOK + r) * 128 + h * HD + c4) =
            *(const float4*)(Os + r * OROW2 + c4);
    }
}

// ================================================================ launch
extern "C" void kernel_launch(void* const* d_in, const int* in_sizes, int n_in,
                              void* d_out, int out_size) {
    const float* x    = (const float*)d_in[0];
    const float* mask = (const float*)d_in[1];
    const float* qkvw = (const float*)d_in[2];
    const float* pw   = (const float*)d_in[3];
    const float* pb   = (const float*)d_in[4];
    const float* bt   = (const float*)d_in[5];
    const float* al   = (const float*)d_in[6];
    const int*   ri   = (const int*)d_in[7];
    float* out = (float*)d_out;

    int B    = in_sizes[0] / (NTOK * CDIM);
    int NW   = in_sizes[1] / (NTOK * NTOK);
    int Mtot = B * NTOK;
    int mblks = (Mtot + 63) / 64;

    cudaFuncSetAttribute(gemm_kernel<false>, cudaFuncAttributeMaxDynamicSharedMemorySize, K1_SMEM);
    cudaFuncSetAttribute(gemm_kernel<true>,  cudaFuncAttributeMaxDynamicSharedMemorySize, K1_SMEM);
    cudaFuncSetAttribute(attn_kernel,        cudaFuncAttributeMaxDynamicSharedMemorySize, SMEM2);

    rpb_kernel<<<(NTOK * NTOK + 255) / 256, 256>>>(bt, ri);
    gemm_kernel<false><<<dim3(mblks, 3), 256, K1_SMEM>>>(x, qkvw, nullptr, nullptr, Mtot);
    attn_kernel<<<dim3(B, HEADS), 256, SMEM2>>>(mask, al, NW);
    gemm_kernel<true><<<dim3(mblks, 1), 256, K1_SMEM>>>(nullptr, pw, pb, out, Mtot);
}

// round 11
// speedup vs baseline: 1.4703x; 1.0590x over previous
#include <cuda_runtime.h>
#include <cstdint>
#include <cstddef>

#define NTOK   49
#define CDIM   128
#define HEADS  4
#define HD     32
#define MAXTOK (8192 * 49)

// scratch (device globals: allocation-free rule)
__device__ float g_qkv[(size_t)MAXTOK * 384];   // [token][384]
__device__ float g_o  [(size_t)MAXTOK * 128];   // [token][128]
__device__ float g_rpb[HEADS * NTOK * NTOK];    // [h][i][j] precomputed bias gather

// ---------------------------------------------------------------- helpers
__device__ __forceinline__ float tf32r(float x) {
    uint32_t u;
    asm("cvt.rna.tf32.f32 %0, %1;" : "=r"(u) : "f"(x));
    return __uint_as_float(u);
}
// logical col -> physical col within its 8-group: [0,4,1,5,2,6,3,7]
__device__ __forceinline__ int permc(int c) {
    return (c & ~7) | (((c & 3) << 1) | ((c >> 2) & 1));
}
__device__ __forceinline__ void mma8(float* d, const uint32_t* a, const uint32_t* b) {
    asm volatile(
        "mma.sync.aligned.m16n8k8.row.col.f32.tf32.tf32.f32 "
        "{%0,%1,%2,%3}, {%4,%5,%6,%7}, {%8,%9}, {%0,%1,%2,%3};\n"
        : "+f"(d[0]), "+f"(d[1]), "+f"(d[2]), "+f"(d[3])
        : "r"(a[0]), "r"(a[1]), "r"(a[2]), "r"(a[3]), "r"(b[0]), "r"(b[1]));
}
__device__ __forceinline__ void ldA(uint32_t* af, const float* base, int row, int stride, int kk2t) {
    float2 p0 = *(const float2*)(base + row * stride + kk2t);
    float2 p1 = *(const float2*)(base + (row + 8) * stride + kk2t);
    af[0] = __float_as_uint(p0.x);
    af[1] = __float_as_uint(p1.x);
    af[2] = __float_as_uint(p0.y);
    af[3] = __float_as_uint(p1.y);
}
__device__ __forceinline__ void ldB(uint32_t* bf, const float* base, int row, int stride, int kk2t) {
    float2 q = *(const float2*)(base + row * stride + kk2t);
    bf[0] = __float_as_uint(q.x);
    bf[1] = __float_as_uint(q.y);
}
__device__ __forceinline__ void st_ipair8(float* dst, float4 lo, float4 hi) {
    float4 o0, o1;
    o0.x = tf32r(lo.x); o0.y = tf32r(hi.x); o0.z = tf32r(lo.y); o0.w = tf32r(hi.y);
    o1.x = tf32r(lo.z); o1.y = tf32r(hi.z); o1.z = tf32r(lo.w); o1.w = tf32r(hi.w);
    *(float4*)(dst)     = o0;
    *(float4*)(dst + 4) = o1;
}

// ================================================================ K0: rpb precompute
__global__ void rpb_kernel(const float* __restrict__ bias_table,
                           const int*   __restrict__ rel_idx) {
    int idx = blockIdx.x * 256 + threadIdx.x;
    if (idx < NTOK * NTOK) {
        int r = rel_idx[idx];
        #pragma unroll
        for (int h = 0; h < HEADS; ++h)
            g_rpb[h * (NTOK * NTOK) + idx] = bias_table[r * HEADS + h];
    }
}

// ================================================================ K1 / K3 GEMM
// C[128 x NB*128] = A[128 x 128] * W[NB*128 x 128]^T  (tf32 mma)
// block tile 128x128, 8 warps of 32x64 (2m x 8n frags); A staged once, W k-chunked;
// epilogue stores straight from accumulators (STG.64, no smem round trip).
#define AROW   136                  // A stride (mod 32 == 8)
#define WKR    40                   // W chunk stride (mod 32 == 8)
#define G2_W   (128 * AROW)         // 17408
#define G2_SMEM ((G2_W + 128 * WKR) * 4)   // 90112 bytes -> 2 CTAs/SM

template <int NB, bool PROJ>
__global__ __launch_bounds__(256, 2)
void gemm_kernel(const float* __restrict__ a_glob,
                 const float* __restrict__ w,
                 const float* __restrict__ pb,
                 float* __restrict__ outp,
                 int Mtot)
{
    extern __shared__ float sm[];
    float* Xs = sm;
    float* Ws = sm + G2_W;
    const int tid  = threadIdx.x;
    const int wid  = tid >> 5;
    const int lane = tid & 31;
    const int g    = lane >> 2;
    const int t    = lane & 3;
    const int t2   = t << 1;
    const int rowbase = blockIdx.x * 128;
    const float* A = PROJ ? g_o : a_glob;

    // stage A tile (128 x 128, full k) into ipair layout -- once per CTA
    for (int i = tid; i < 128 * 16; i += 256) {
        int r = i >> 4, c8 = (i & 15) << 3;
        int grow = rowbase + r; if (grow >= Mtot) grow = Mtot - 1;
        const float* src = A + (size_t)grow * CDIM + c8;
        st_ipair8(Xs + r * AROW + c8, *(const float4*)src, *(const float4*)(src + 4));
    }

    const int mh = wid >> 1;        // 0..3 : 32-row group
    const int nh = wid & 1;         // 0..1 : 64-col half

    for (int nb = 0; nb < NB; ++nb) {
        float acc[2][8][4];
        #pragma unroll
        for (int mi = 0; mi < 2; ++mi)
            #pragma unroll
            for (int nt = 0; nt < 8; ++nt)
                #pragma unroll
                for (int e = 0; e < 4; ++e) acc[mi][nt][e] = 0.f;

        for (int kc = 0; kc < 4; ++kc) {          // stream W in k-chunks of 32
            __syncthreads();                       // Ws reuse guard (also covers A stage at kc=0,nb=0)
            for (int i = tid; i < 128 * 4; i += 256) {
                int n = i >> 2, c8 = (i & 3) << 3;
                const float* src = w + (size_t)(nb * 128 + n) * CDIM + kc * 32 + c8;
                st_ipair8(Ws + n * WKR + c8, *(const float4*)src, *(const float4*)(src + 4));
            }
            __syncthreads();
            #pragma unroll
            for (int k8 = 0; k8 < 4; ++k8) {
                const int kp = k8 * 8 + t2;
                uint32_t af0[4], af1[4];
                ldA(af0, Xs, mh * 32 + g,      AROW, kc * 32 + kp);
                ldA(af1, Xs, mh * 32 + 16 + g, AROW, kc * 32 + kp);
                #pragma unroll
                for (int nt = 0; nt < 8; ++nt) {
                    uint32_t bf[2];
                    ldB(bf, Ws, nh * 64 + nt * 8 + g, WKR, kp);
                    mma8(acc[0][nt], af0, bf);
                    mma8(acc[1][nt], af1, bf);
                }
            }
        }

        // epilogue: direct STG.64 from accumulators (C pairs are adjacent cols 2t,2t+1)
        #pragma unroll
        for (int mi = 0; mi < 2; ++mi)
            #pragma unroll
            for (int nt = 0; nt < 8; ++nt) {
                int col = nh * 64 + nt * 8 + 2 * t;
                #pragma unroll
                for (int half = 0; half < 2; ++half) {
                    int row = rowbase + mh * 32 + mi * 16 + g + half * 8;
                    if (row < Mtot) {
                        float2 v = make_float2(acc[mi][nt][half * 2], acc[mi][nt][half * 2 + 1]);
                        if (PROJ) {
                            v.x += pb[col];
                            v.y += pb[col + 1];
                            *(float2*)(outp + (size_t)row * 128 + col) = v;
                        } else {
                            *(float2*)(g_qkv + (size_t)row * 384 + nb * 128 + col) = v;
                        }
                    }
                }
            }
    }
}

// ================================================================ K2: attention
// one CTA per (window, head); 256 threads; rpb/mask read directly from global
#define QROW2  40
#define VROW2  56
#define PROW2  56
#define OROW2  36
#define OFF2_Q 0                       // 64*40 = 2560 (later aliased by O, stride 36)
#define OFF2_K (OFF2_Q + 64 * QROW2)   // 56*40 = 2240
#define OFF2_V (OFF2_K + 56 * QROW2)   // 32*56 = 1792
#define OFF2_P (OFF2_V + HD * VROW2)   // 64*56 = 3584
#define SMEM2  ((OFF2_P + 64 * PROW2) * 4)   // 40704 bytes -> 5 CTAs/SM

__global__ __launch_bounds__(256)
void attn_kernel(const float* __restrict__ mask,
                 const float* __restrict__ alpha,
                 int nwin)
{
    extern __shared__ float sm[];
    const int b    = blockIdx.x;
    const int h    = blockIdx.y;
    const int tid  = threadIdx.x;
    const int wid  = tid >> 5;
    const int lane = tid & 31;
    const int g    = lane >> 2;
    const int t    = lane & 3;
    const int t2   = t << 1;

    float* Qs = sm + OFF2_Q;
    float* Ks = sm + OFF2_K;
    float* Vs = sm + OFF2_V;
    float* Ps = sm + OFF2_P;
    float* Os = sm + OFF2_Q;      // O aliases Q (Q dead after S-mma)

    const float* mb  = mask + (size_t)(b % nwin) * (NTOK * NTOK);
    const float* rpb = g_rpb + h * (NTOK * NTOK);

    // zero V (incl. token-pad cols) before scattered fills
    for (int i = tid; i < HD * VROW2; i += 256) Vs[i] = 0.f;
    __syncthreads();

    // stage q, k (head-dim ipair-permuted), v (transposed, token ipair-permuted, tf32)
    const float* qb = g_qkv + (size_t)(b * NTOK) * 384 + h * HD;
    for (int i = tid; i < NTOK * HD; i += 256) {
        int r = i >> 5, d = i & 31;
        int col = permc(d);
        Qs[r * QROW2 + col] = qb[(size_t)r * 384 + d];
        Ks[r * QROW2 + col] = qb[(size_t)r * 384 + 128 + d];
        Vs[d * VROW2 + permc(r)] = tf32r(qb[(size_t)r * 384 + 256 + d]);
    }
    __syncthreads();

    // L2 normalize q (alpha folded) / k; 4-row ILP
    {
        const bool isQ = (wid < 4);
        const int  part = wid & 3;
        const float sc = isQ ? alpha[h] : 1.f;
        float* T = isQ ? Qs : Ks;
        const int rs = part * 13;
        const int re = min(rs + 13, NTOK);
        for (int r = rs; r < re; r += 4) {
            float v[4], ss[4]; int rr[4];
            #pragma unroll
            for (int j = 0; j < 4; ++j) {
                rr[j] = min(r + j, re - 1);
                v[j]  = T[rr[j] * QROW2 + lane];
                ss[j] = v[j] * v[j];
            }
            #pragma unroll
            for (int o = 16; o > 0; o >>= 1) {
                #pragma unroll
                for (int j = 0; j < 4; ++j) ss[j] += __shfl_xor_sync(0xffffffffu, ss[j], o);
            }
            #pragma unroll
            for (int j = 0; j < 4; ++j) {
                if (r + j < re) {
                    float inv = sc / (sqrtf(ss[j]) + 1e-6f);
                    T[rr[j] * QROW2 + lane] = tf32r(v[j] * inv);
                }
            }
        }
    }
    __syncthreads();

    // S = q_hat k_hat^T + rpb + mask (both straight from global); pad cols -> -1e30
    if (wid < 7) {
        const int nt = wid;
        uint32_t bfv[4][2];
        #pragma unroll
        for (int k8 = 0; k8 < 4; ++k8)
            ldB(bfv[k8], Ks, nt * 8 + g, QROW2, k8 * 8 + t2);
        #pragma unroll
        for (int mt = 0; mt < 4; ++mt) {
            float c[4] = {0.f, 0.f, 0.f, 0.f};
            #pragma unroll
            for (int k8 = 0; k8 < 4; ++k8) {
                uint32_t af[4];
                ldA(af, Qs, mt * 16 + g, QROW2, k8 * 8 + t2);
                mma8(c, af, bfv[k8]);
            }
            #pragma unroll
            for (int e = 0; e < 4; ++e) {
                int i = mt * 16 + g + (e >> 1) * 8;
                int j = nt * 8 + 2 * t + (e & 1);
                float v;
                if (j >= NTOK)       v = -1e30f;
                else if (i < NTOK)   v = c[e] + rpb[i * NTOK + j] + mb[i * NTOK + j];
                else                 v = c[e];
                Ps[i * PROW2 + permc(j)] = v;
            }
        }
    }
    __syncthreads();

    // row softmax (no max-subtract; logits bounded); pads -1e30 -> exp 0
    {
        for (int i0 = wid; i0 < NTOK; i0 += 16) {
            const int ia = i0;
            const int ib = i0 + 8;
            const bool hasb = (ib < NTOK);
            const int ibc = hasb ? ib : ia;
            float e1a = __expf(Ps[ia * PROW2 + lane]);
            float e2a = (lane < 24) ? __expf(Ps[ia * PROW2 + 32 + lane]) : 0.f;
            float e1b = __expf(Ps[ibc * PROW2 + lane]);
            float e2b = (lane < 24) ? __expf(Ps[ibc * PROW2 + 32 + lane]) : 0.f;
            float sa = e1a + e2a;
            float sb = e1b + e2b;
            #pragma unroll
            for (int o = 16; o > 0; o >>= 1) {
                sa += __shfl_xor_sync(0xffffffffu, sa, o);
                sb += __shfl_xor_sync(0xffffffffu, sb, o);
            }
            float inva = 1.f / sa;
            Ps[ia * PROW2 + lane] = tf32r(e1a * inva);
            if (lane < 24) Ps[ia * PROW2 + 32 + lane] = tf32r(e2a * inva);
            if (hasb) {
                float invb = 1.f / sb;
                Ps[ib * PROW2 + lane] = tf32r(e1b * invb);
                if (lane < 24) Ps[ib * PROW2 + 32 + lane] = tf32r(e2b * invb);
            }
        }
    }
    __syncthreads();

    // O = P V  (V^T layout): 4 nt x 4 mt over 8 warps; O -> Os (stride 36, logical cols)
    {
        const int nt  = wid >> 1;
        const int mt0 = (wid & 1) * 2;
        uint32_t bfv[7][2];
        #pragma unroll
        for (int k8 = 0; k8 < 7; ++k8)
            ldB(bfv[k8], Vs, nt * 8 + g, VROW2, k8 * 8 + t2);
        #pragma unroll
        for (int mi = 0; mi < 2; ++mi) {
            const int mt = mt0 + mi;
            float c[4] = {0.f, 0.f, 0.f, 0.f};
            #pragma unroll
            for (int k8 = 0; k8 < 7; ++k8) {
                uint32_t af[4];
                ldA(af, Ps, mt * 16 + g, PROW2, k8 * 8 + t2);
                mma8(c, af, bfv[k8]);
            }
            #pragma unroll
            for (int e = 0; e < 4; ++e) {
                int i = mt * 16 + g + (e >> 1) * 8;
                if (i >= NTOK) continue;
                int d = nt * 8 + 2 * t + (e & 1);
                Os[i * OROW2 + d] = tf32r(c[e]);
            }
        }
    }
    __syncthreads();

    // coalesced O write to global
    for (int i = tid; i < NTOK * 8; i += 256) {
        int r = i >> 3, c4 = (i & 7) << 2;
        *(float4*)(g_o + (size_t)(b * NTOK + r) * 128 + h * HD + c4) =
            *(const float4*)(Os + r * OROW2 + c4);
    }
}

// ================================================================ launch
extern "C" void kernel_launch(void* const* d_in, const int* in_sizes, int n_in,
                              void* d_out, int out_size) {
    const float* x    = (const float*)d_in[0];
    const float* mask = (const float*)d_in[1];
    const float* qkvw = (const float*)d_in[2];
    const float* pw   = (const float*)d_in[3];
    const float* pb   = (const float*)d_in[4];
    const float* bt   = (const float*)d_in[5];
    const float* al   = (const float*)d_in[6];
    const int*   ri   = (const int*)d_in[7];
    float* out = (float*)d_out;

    int B    = in_sizes[0] / (NTOK * CDIM);
    int NW   = in_sizes[1] / (NTOK * NTOK);
    int Mtot = B * NTOK;
    int mblks = (Mtot + 127) / 128;

    cudaFuncSetAttribute((const void*)gemm_kernel<3, false>, cudaFuncAttributeMaxDynamicSharedMemorySize, G2_SMEM);
    cudaFuncSetAttribute((const void*)gemm_kernel<1, true>,  cudaFuncAttributeMaxDynamicSharedMemorySize, G2_SMEM);
    cudaFuncSetAttribute((const void*)attn_kernel,           cudaFuncAttributeMaxDynamicSharedMemorySize, SMEM2);

    rpb_kernel<<<(NTOK * NTOK + 255) / 256, 256>>>(bt, ri);
    gemm_kernel<3, false><<<mblks, 256, G2_SMEM>>>(x, qkvw, nullptr, nullptr, Mtot);
    attn_kernel<<<dim3(B, HEADS), 256, SMEM2>>>(mask, al, NW);
    gemm_kernel<1, true><<<mblks, 256, G2_SMEM>>>(nullptr, pw, pb, out, Mtot);
}

// round 12
// speedup vs baseline: 1.5492x; 1.0537x over previous
#include <cuda_runtime.h>
#include <cstdint>
#include <cstddef>

#define NTOK   49
#define CDIM   128
#define HEADS  4
#define HD     32
#define MAXTOK (8192 * 49)

// scratch (device globals: allocation-free rule)
__device__ float g_qkv[(size_t)MAXTOK * 384];   // [token][384]
__device__ float g_o  [(size_t)MAXTOK * 128];   // [token][128]
__device__ float g_rpb[HEADS * NTOK * NTOK];    // [h][i][j] precomputed bias gather

// ---------------------------------------------------------------- helpers
__device__ __forceinline__ float tf32r(float x) {
    uint32_t u;
    asm("cvt.rna.tf32.f32 %0, %1;" : "=r"(u) : "f"(x));
    return __uint_as_float(u);
}
// logical col -> physical col within its 8-group: [0,4,1,5,2,6,3,7]
__device__ __forceinline__ int permc(int c) {
    return (c & ~7) | (((c & 3) << 1) | ((c >> 2) & 1));
}
__device__ __forceinline__ void mma8(float* d, const uint32_t* a, const uint32_t* b) {
    asm volatile(
        "mma.sync.aligned.m16n8k8.row.col.f32.tf32.tf32.f32 "
        "{%0,%1,%2,%3}, {%4,%5,%6,%7}, {%8,%9}, {%0,%1,%2,%3};\n"
        : "+f"(d[0]), "+f"(d[1]), "+f"(d[2]), "+f"(d[3])
        : "r"(a[0]), "r"(a[1]), "r"(a[2]), "r"(a[3]), "r"(b[0]), "r"(b[1]));
}
__device__ __forceinline__ void ldA(uint32_t* af, const float* base, int row, int stride, int kk2t) {
    float2 p0 = *(const float2*)(base + row * stride + kk2t);
    float2 p1 = *(const float2*)(base + (row + 8) * stride + kk2t);
    af[0] = __float_as_uint(p0.x);
    af[1] = __float_as_uint(p1.x);
    af[2] = __float_as_uint(p0.y);
    af[3] = __float_as_uint(p1.y);
}
__device__ __forceinline__ void ldB(uint32_t* bf, const float* base, int row, int stride, int kk2t) {
    float2 q = *(const float2*)(base + row * stride + kk2t);
    bf[0] = __float_as_uint(q.x);
    bf[1] = __float_as_uint(q.y);
}
__device__ __forceinline__ void st_ipair8(float* dst, float4 lo, float4 hi) {
    float4 o0, o1;
    o0.x = tf32r(lo.x); o0.y = tf32r(hi.x); o0.z = tf32r(lo.y); o0.w = tf32r(hi.y);
    o1.x = tf32r(lo.z); o1.y = tf32r(hi.z); o1.z = tf32r(lo.w); o1.w = tf32r(hi.w);
    *(float4*)(dst)     = o0;
    *(float4*)(dst + 4) = o1;
}

// ================================================================ K0: rpb precompute
__global__ void rpb_kernel(const float* __restrict__ bias_table,
                           const int*   __restrict__ rel_idx) {
    int idx = blockIdx.x * 256 + threadIdx.x;
    if (idx < NTOK * NTOK) {
        int r = rel_idx[idx];
        #pragma unroll
        for (int h = 0; h < HEADS; ++h)
            g_rpb[h * (NTOK * NTOK) + idx] = bias_table[r * HEADS + h];
    }
}

// ================================================================ K1 / K3 GEMM
// C[128 x NB*128] = A[128 x 128] * W[NB*128 x 128]^T  (tf32 mma)
// block tile 128x128, 8 warps of 32x64 (2m x 8n); A staged once; W software-
// pipelined in 32-k chunks through a double smem buffer (LDG before mma,
// STS after mma, one sync per chunk). Epilogue = direct STG.64 from regs.
#define AROW   136                  // A stride (mod 32 == 8)
#define WKR    40                   // W chunk stride (mod 32 == 8)
#define G2_W   (128 * AROW)         // 17408 floats
#define WCH    (128 * WKR)          // 5120 floats per W buffer
#define G2_SMEM ((G2_W + 2 * WCH) * 4)   // 110592 bytes -> 2 CTAs/SM

struct WPref { float4 lo[2], hi[2]; };

__device__ __forceinline__ void ldg_chunk(const float* __restrict__ w, int cid, int tid, WPref& p) {
    const int nb = cid >> 2, kc = cid & 3;
    #pragma unroll
    for (int j = 0; j < 2; ++j) {
        int i = tid + j * 256;                 // 512 items: 128 rows x 4 col-groups
        int n = i >> 2, c8 = (i & 3) << 3;
        const float* src = w + (size_t)(nb * 128 + n) * CDIM + kc * 32 + c8;
        p.lo[j] = *(const float4*)src;
        p.hi[j] = *(const float4*)(src + 4);
    }
}
__device__ __forceinline__ void sts_chunk(float* Ws, int tid, const WPref& p) {
    #pragma unroll
    for (int j = 0; j < 2; ++j) {
        int i = tid + j * 256;
        int n = i >> 2, c8 = (i & 3) << 3;
        st_ipair8(Ws + n * WKR + c8, p.lo[j], p.hi[j]);
    }
}

template <int NB, bool PROJ>
__global__ __launch_bounds__(256, 2)
void gemm_kernel(const float* __restrict__ a_glob,
                 const float* __restrict__ w,
                 const float* __restrict__ pb,
                 float* __restrict__ outp,
                 int Mtot)
{
    extern __shared__ float sm[];
    float* Xs = sm;
    float* Wb0 = sm + G2_W;
    float* Wb1 = sm + G2_W + WCH;
    const int tid  = threadIdx.x;
    const int wid  = tid >> 5;
    const int lane = tid & 31;
    const int g    = lane >> 2;
    const int t    = lane & 3;
    const int t2   = t << 1;
    const int rowbase = blockIdx.x * 128;
    const float* A = PROJ ? g_o : a_glob;

    // prologue: prefetch W chunk 0 (LDG first so it overlaps A staging)
    WPref pf;
    ldg_chunk(w, 0, tid, pf);

    // stage A tile (128 x 128, full k) into ipair layout -- once per CTA
    for (int i = tid; i < 128 * 16; i += 256) {
        int r = i >> 4, c8 = (i & 15) << 3;
        int grow = rowbase + r; if (grow >= Mtot) grow = Mtot - 1;
        const float* src = A + (size_t)grow * CDIM + c8;
        st_ipair8(Xs + r * AROW + c8, *(const float4*)src, *(const float4*)(src + 4));
    }
    sts_chunk(Wb0, tid, pf);
    __syncthreads();

    const int mh = wid >> 1;        // 0..3 : 32-row group
    const int nh = wid & 1;         // 0..1 : 64-col half
    const int total = NB * 4;

    float acc[2][8][4];
    for (int cid = 0; cid < total; ++cid) {
        const int nb = cid >> 2, kc = cid & 3;
        float* Ws = (cid & 1) ? Wb1 : Wb0;
        float* Wn = (cid & 1) ? Wb0 : Wb1;

        if (kc == 0) {
            #pragma unroll
            for (int mi = 0; mi < 2; ++mi)
                #pragma unroll
                for (int nt = 0; nt < 8; ++nt)
                    #pragma unroll
                    for (int e = 0; e < 4; ++e) acc[mi][nt][e] = 0.f;
        }

        WPref nxt;
        if (cid + 1 < total) ldg_chunk(w, cid + 1, tid, nxt);   // in-flight during mma

        #pragma unroll
        for (int k8 = 0; k8 < 4; ++k8) {
            const int kp = k8 * 8 + t2;
            uint32_t af0[4], af1[4];
            ldA(af0, Xs, mh * 32 + g,      AROW, kc * 32 + kp);
            ldA(af1, Xs, mh * 32 + 16 + g, AROW, kc * 32 + kp);
            #pragma unroll
            for (int nt = 0; nt < 8; ++nt) {
                uint32_t bf[2];
                ldB(bf, Ws, nh * 64 + nt * 8 + g, WKR, kp);
                mma8(acc[0][nt], af0, bf);
                mma8(acc[1][nt], af1, bf);
            }
        }

        if (cid + 1 < total) sts_chunk(Wn, tid, nxt);

        if (kc == 3) {
            // epilogue: direct STG.64 from accumulators (C pairs = adjacent cols)
            #pragma unroll
            for (int mi = 0; mi < 2; ++mi)
                #pragma unroll
                for (int nt = 0; nt < 8; ++nt) {
                    int col = nh * 64 + nt * 8 + 2 * t;
                    #pragma unroll
                    for (int half = 0; half < 2; ++half) {
                        int row = rowbase + mh * 32 + mi * 16 + g + half * 8;
                        if (row < Mtot) {
                            float2 v = make_float2(acc[mi][nt][half * 2], acc[mi][nt][half * 2 + 1]);
                            if (PROJ) {
                                v.x += pb[col];
                                v.y += pb[col + 1];
                                *(float2*)(outp + (size_t)row * 128 + col) = v;
                            } else {
                                *(float2*)(g_qkv + (size_t)row * 384 + nb * 128 + col) = v;
                            }
                        }
                    }
                }
        }
        __syncthreads();
    }
}

// ================================================================ K2: attention
// one CTA per (window, head); 256 threads; rpb/mask read directly from global
#define QROW2  40
#define VROW2  56
#define PROW2  56
#define OROW2  36
#define OFF2_Q 0                       // 64*40 = 2560 (later aliased by O, stride 36)
#define OFF2_K (OFF2_Q + 64 * QROW2)   // 56*40 = 2240
#define OFF2_V (OFF2_K + 56 * QROW2)   // 32*56 = 1792
#define OFF2_P (OFF2_V + HD * VROW2)   // 64*56 = 3584
#define SMEM2  ((OFF2_P + 64 * PROW2) * 4)   // 40704 bytes -> 5 CTAs/SM

__global__ __launch_bounds__(256)
void attn_kernel(const float* __restrict__ mask,
                 const float* __restrict__ alpha,
                 int nwin)
{
    extern __shared__ float sm[];
    const int b    = blockIdx.x;
    const int h    = blockIdx.y;
    const int tid  = threadIdx.x;
    const int wid  = tid >> 5;
    const int lane = tid & 31;
    const int g    = lane >> 2;
    const int t    = lane & 3;
    const int t2   = t << 1;

    float* Qs = sm + OFF2_Q;
    float* Ks = sm + OFF2_K;
    float* Vs = sm + OFF2_V;
    float* Ps = sm + OFF2_P;
    float* Os = sm + OFF2_Q;      // O aliases Q (Q dead after S-mma)

    const float* mb  = mask + (size_t)(b % nwin) * (NTOK * NTOK);
    const float* rpb = g_rpb + h * (NTOK * NTOK);

    // zero V (incl. token-pad cols) before scattered fills
    for (int i = tid; i < HD * VROW2; i += 256) Vs[i] = 0.f;
    __syncthreads();

    // stage q, k (head-dim ipair-permuted), v (transposed, token ipair-permuted, tf32)
    const float* qb = g_qkv + (size_t)(b * NTOK) * 384 + h * HD;
    for (int i = tid; i < NTOK * HD; i += 256) {
        int r = i >> 5, d = i & 31;
        int col = permc(d);
        Qs[r * QROW2 + col] = qb[(size_t)r * 384 + d];
        Ks[r * QROW2 + col] = qb[(size_t)r * 384 + 128 + d];
        Vs[d * VROW2 + permc(r)] = tf32r(qb[(size_t)r * 384 + 256 + d]);
    }
    __syncthreads();

    // L2 normalize q (alpha folded) / k; 4-row ILP
    {
        const bool isQ = (wid < 4);
        const int  part = wid & 3;
        const float sc = isQ ? alpha[h] : 1.f;
        float* T = isQ ? Qs : Ks;
        const int rs = part * 13;
        const int re = min(rs + 13, NTOK);
        for (int r = rs; r < re; r += 4) {
            float v[4], ss[4]; int rr[4];
            #pragma unroll
            for (int j = 0; j < 4; ++j) {
                rr[j] = min(r + j, re - 1);
                v[j]  = T[rr[j] * QROW2 + lane];
                ss[j] = v[j] * v[j];
            }
            #pragma unroll
            for (int o = 16; o > 0; o >>= 1) {
                #pragma unroll
                for (int j = 0; j < 4; ++j) ss[j] += __shfl_xor_sync(0xffffffffu, ss[j], o);
            }
            #pragma unroll
            for (int j = 0; j < 4; ++j) {
                if (r + j < re) {
                    float inv = sc / (sqrtf(ss[j]) + 1e-6f);
                    T[rr[j] * QROW2 + lane] = tf32r(v[j] * inv);
                }
            }
        }
    }
    __syncthreads();

    // S = q_hat k_hat^T + rpb + mask (both straight from global); pad cols -> -1e30
    if (wid < 7) {
        const int nt = wid;
        uint32_t bfv[4][2];
        #pragma unroll
        for (int k8 = 0; k8 < 4; ++k8)
            ldB(bfv[k8], Ks, nt * 8 + g, QROW2, k8 * 8 + t2);
        #pragma unroll
        for (int mt = 0; mt < 4; ++mt) {
            float c[4] = {0.f, 0.f, 0.f, 0.f};
            #pragma unroll
            for (int k8 = 0; k8 < 4; ++k8) {
                uint32_t af[4];
                ldA(af, Qs, mt * 16 + g, QROW2, k8 * 8 + t2);
                mma8(c, af, bfv[k8]);
            }
            #pragma unroll
            for (int e = 0; e < 4; ++e) {
                int i = mt * 16 + g + (e >> 1) * 8;
                int j = nt * 8 + 2 * t + (e & 1);
                float v;
                if (j >= NTOK)       v = -1e30f;
                else if (i < NTOK)   v = c[e] + rpb[i * NTOK + j] + mb[i * NTOK + j];
                else                 v = c[e];
                Ps[i * PROW2 + permc(j)] = v;
            }
        }
    }
    __syncthreads();

    // row softmax (no max-subtract; logits bounded); pads -1e30 -> exp 0
    {
        for (int i0 = wid; i0 < NTOK; i0 += 16) {
            const int ia = i0;
            const int ib = i0 + 8;
            const bool hasb = (ib < NTOK);
            const int ibc = hasb ? ib : ia;
            float e1a = __expf(Ps[ia * PROW2 + lane]);
            float e2a = (lane < 24) ? __expf(Ps[ia * PROW2 + 32 + lane]) : 0.f;
            float e1b = __expf(Ps[ibc * PROW2 + lane]);
            float e2b = (lane < 24) ? __expf(Ps[ibc * PROW2 + 32 + lane]) : 0.f;
            float sa = e1a + e2a;
            float sb = e1b + e2b;
            #pragma unroll
            for (int o = 16; o > 0; o >>= 1) {
                sa += __shfl_xor_sync(0xffffffffu, sa, o);
                sb += __shfl_xor_sync(0xffffffffu, sb, o);
            }
            float inva = 1.f / sa;
            Ps[ia * PROW2 + lane] = tf32r(e1a * inva);
            if (lane < 24) Ps[ia * PROW2 + 32 + lane] = tf32r(e2a * inva);
            if (hasb) {
                float invb = 1.f / sb;
                Ps[ib * PROW2 + lane] = tf32r(e1b * invb);
                if (lane < 24) Ps[ib * PROW2 + 32 + lane] = tf32r(e2b * invb);
            }
        }
    }
    __syncthreads();

    // O = P V  (V^T layout): 4 nt x 4 mt over 8 warps; O -> Os (stride 36, logical cols)
    {
        const int nt  = wid >> 1;
        const int mt0 = (wid & 1) * 2;
        uint32_t bfv[7][2];
        #pragma unroll
        for (int k8 = 0; k8 < 7; ++k8)
            ldB(bfv[k8], Vs, nt * 8 + g, VROW2, k8 * 8 + t2);
        #pragma unroll
        for (int mi = 0; mi < 2; ++mi) {
            const int mt = mt0 + mi;
            float c[4] = {0.f, 0.f, 0.f, 0.f};
            #pragma unroll
            for (int k8 = 0; k8 < 7; ++k8) {
                uint32_t af[4];
                ldA(af, Ps, mt * 16 + g, PROW2, k8 * 8 + t2);
                mma8(c, af, bfv[k8]);
            }
            #pragma unroll
            for (int e = 0; e < 4; ++e) {
                int i = mt * 16 + g + (e >> 1) * 8;
                if (i >= NTOK) continue;
                int d = nt * 8 + 2 * t + (e & 1);
                Os[i * OROW2 + d] = tf32r(c[e]);
            }
        }
    }
    __syncthreads();

    // coalesced O write to global
    for (int i = tid; i < NTOK * 8; i += 256) {
        int r = i >> 3, c4 = (i & 7) << 2;
        *(float4*)(g_o + (size_t)(b * NTOK + r) * 128 + h * HD + c4) =
            *(const float4*)(Os + r * OROW2 + c4);
    }
}

// ================================================================ launch
extern "C" void kernel_launch(void* const* d_in, const int* in_sizes, int n_in,
                              void* d_out, int out_size) {
    const float* x    = (const float*)d_in[0];
    const float* mask = (const float*)d_in[1];
    const float* qkvw = (const float*)d_in[2];
    const float* pw   = (const float*)d_in[3];
    const float* pb   = (const float*)d_in[4];
    const float* bt   = (const float*)d_in[5];
    const float* al   = (const float*)d_in[6];
    const int*   ri   = (const int*)d_in[7];
    float* out = (float*)d_out;

    int B    = in_sizes[0] / (NTOK * CDIM);
    int NW   = in_sizes[1] / (NTOK * NTOK);
    int Mtot = B * NTOK;
    int mblks = (Mtot + 127) / 128;

    cudaFuncSetAttribute((const void*)gemm_kernel<3, false>, cudaFuncAttributeMaxDynamicSharedMemorySize, G2_SMEM);
    cudaFuncSetAttribute((const void*)gemm_kernel<1, true>,  cudaFuncAttributeMaxDynamicSharedMemorySize, G2_SMEM);
    cudaFuncSetAttribute((const void*)attn_kernel,           cudaFuncAttributeMaxDynamicSharedMemorySize, SMEM2);

    rpb_kernel<<<(NTOK * NTOK + 255) / 256, 256>>>(bt, ri);
    gemm_kernel<3, false><<<mblks, 256, G2_SMEM>>>(x, qkvw, nullptr, nullptr, Mtot);
    attn_kernel<<<dim3(B, HEADS), 256, SMEM2>>>(mask, al, NW);
    gemm_kernel<1, true><<<mblks, 256, G2_SMEM>>>(nullptr, pw, pb, out, Mtot);
}